// round 16
// baseline (speedup 1.0000x reference)
#include <cuda_runtime.h>
#include <cuda_fp16.h>
#include <mma.h>

using namespace nvcuda;

#define NN 50000
#define EE 800000
#define ECAP (EE + NN)   // padded edge capacity (each row padded to even count)
#define F 64
#define GG 64
#define CC 10
#define NBLK 49      // ceil(NN/1024)
#define PROPBLK 740  // 148 SMs x 5 resident CTAs

typedef unsigned long long ull;

// ---------------- scratch (device globals; no allocation allowed) ----------------
#define WDEG_OFF    0
#define DEGCNT_OFF  (NN * 4)
#define STATE_OFF   (2 * NN * 4)
#define POOLCNT_OFF (STATE_OFF + 64 * 8)
#define ZERO_BYTES  (POOLCNT_OFF + 16)
__device__ __align__(16) unsigned char g_zero[ZERO_BYTES];

__device__ __align__(16) float  g_dinv[NN];
__device__ __align__(16) int    g_rowptr[NN + 1];
__device__ __align__(16) int    g_epos[EE];      // per-edge slot within its row
__device__ __align__(16) int2   g_edges[ECAP];   // (col, bitcast(norm)), even-padded rows
__device__ __align__(16) __half g_xh[NN * F];    // fp16 copy of x
__device__ __align__(16) __half g_T1[NN * F];
__device__ __align__(16) __half g_H0[NN * F];
__device__ __align__(16) __half g_H1[NN * F];
__device__ __align__(16) float  g_Hf[NN * F];    // fp32 final layer output
__device__ __align__(16) float  g_pool[GG * F];
__device__ __align__(16) __half g_Wf[3 * 192 * 64];  // pre-folded fp16 weights

// fp16 pack/unpack helpers (8 bytes = 4 features)
__device__ __forceinline__ float4 h4_to_f4(uint2 u) {
    float2 a = __half22float2(*reinterpret_cast<const __half2*>(&u.x));
    float2 b = __half22float2(*reinterpret_cast<const __half2*>(&u.y));
    return make_float4(a.x, a.y, b.x, b.y);
}
__device__ __forceinline__ uint2 f4_to_h4(float4 v) {
    __half2 a = __floats2half2_rn(v.x, v.y);
    __half2 b = __floats2half2_rn(v.z, v.w);
    uint2 u;
    u.x = *reinterpret_cast<unsigned*>(&a);
    u.y = *reinterpret_cast<unsigned*>(&b);
    return u;
}

// ---------------- x -> fp16 copy ----------------
__global__ void cvt_kernel(const float4* __restrict__ in) {
    int i = blockIdx.x * blockDim.x + threadIdx.x;
    if (i < NN * 16) {
        ((uint2*)g_xh)[i] = f4_to_h4(in[i]);
    }
}

// ---------------- fused build: blocks 0-2 fold W, rest do degree (2 edges/thread) ----
__global__ void degw_kernel(const int* __restrict__ ei, const float* __restrict__ attr,
                            const float* __restrict__ W1, const float* __restrict__ W2,
                            const float* __restrict__ W3) {
    if (blockIdx.x < 3) {
        int b = blockIdx.x;
        const float* W = (b == 0) ? W1 : (b == 1) ? W2 : W3;
        __half* dst = g_Wf + b * 192 * 64;
        int tid = threadIdx.x;
        for (int i = tid; i < 1024; i += 256) {
            int k = i >> 4, c = i & 15;
            float4 w0 = ((const float4*)W)[i];
            float4 w1 = ((const float4*)W)[1024 + i];
            float4 w2 = ((const float4*)W)[2048 + i];
            float4 f0 = make_float4(w0.x - w2.x, w0.y - w2.y, w0.z - w2.z, w0.w - w2.w);
            float4 f2 = make_float4(2.f * w2.x, 2.f * w2.y, 2.f * w2.z, 2.f * w2.w);
            *(uint2*)&dst[k * 64 + c * 4]         = f4_to_h4(f0);
            *(uint2*)&dst[(64 + k) * 64 + c * 4]  = f4_to_h4(w1);
            *(uint2*)&dst[(128 + k) * 64 + c * 4] = f4_to_h4(f2);
        }
        return;
    }
    float* wdeg = (float*)(g_zero + WDEG_OFF);
    int* degcnt = (int*)(g_zero + DEGCNT_OFF);
    int t = (blockIdx.x - 3) * blockDim.x + threadIdx.x;
    int e0 = t * 2;
    if (e0 + 1 < EE) {
        int2 r2 = *(const int2*)(ei + e0);
        float2 a2 = *(const float2*)(attr + e0);
        atomicAdd(&wdeg[r2.x], a2.x);
        atomicAdd(&wdeg[r2.y], a2.y);
        g_epos[e0]     = atomicAdd(&degcnt[r2.x], 1);
        g_epos[e0 + 1] = atomicAdd(&degcnt[r2.y], 1);
    } else if (e0 < EE) {
        int r = ei[e0];
        atomicAdd(&wdeg[r], attr[e0]);
        g_epos[e0] = atomicAdd(&degcnt[r], 1);
    }
}

// Single-kernel scan over EVEN-PADDED degrees + dinv + rowptr init + hole edges.
__global__ void scan_kernel() {
    float* wdeg = (float*)(g_zero + WDEG_OFF);
    int* degcnt = (int*)(g_zero + DEGCNT_OFF);
    volatile ull* state = (volatile ull*)(g_zero + STATE_OFF);

    int tid = threadIdx.x;
    int b = blockIdx.x;
    int i = b * 1024 + tid;
    int deg = (i < NN) ? degcnt[i] : 0;
    int pdeg = (deg + 1) & ~1;   // padded to even

    if (i < NN) {
        float d = wdeg[i];
        g_dinv[i] = (d > 0.f) ? rsqrtf(d) : 0.f;
    }

    int lane = tid & 31, wid = tid >> 5;
    int x = pdeg;
    #pragma unroll
    for (int o = 1; o < 32; o <<= 1) {
        int y = __shfl_up_sync(0xFFFFFFFFu, x, o);
        if (lane >= o) x += y;
    }
    __shared__ int ws[32];
    __shared__ int s_prefix;
    if (lane == 31) ws[wid] = x;
    __syncthreads();
    if (wid == 0) {
        int s = ws[lane];
        #pragma unroll
        for (int o = 1; o < 32; o <<= 1) {
            int y = __shfl_up_sync(0xFFFFFFFFu, s, o);
            if (lane >= o) s += y;
        }
        ws[lane] = s;
    }
    __syncthreads();
    int blocksum = ws[31];

    if (tid == 0) {
        atomicExch((ull*)&state[b], (1ull << 32) | (unsigned)blocksum);
    }
    if (tid < 32) {
        int acc = 0;
        for (int p = tid; p < b; p += 32) {
            ull sv;
            do { sv = state[p]; } while ((sv >> 32) == 0);
            acc += (int)(unsigned)sv;
        }
        #pragma unroll
        for (int o = 16; o > 0; o >>= 1) acc += __shfl_down_sync(0xFFFFFFFFu, acc, o);
        if (tid == 0) s_prefix = acc;
    }
    __syncthreads();

    int excl = x - pdeg + (wid > 0 ? ws[wid - 1] : 0);
    if (i < NN) {
        int r = excl + s_prefix;
        g_rowptr[i] = r;
        if (deg & 1) g_edges[r + deg] = make_int2(0, 0);  // neutral hole edge
    }
    if (b == NBLK - 1 && tid == 0) g_rowptr[NN] = s_prefix + blocksum;
}

// Atomic-free fill: slot precomputed in degw (epos), pure scatter stores.
__global__ void fill_kernel(const int* __restrict__ ei, const float* __restrict__ attr) {
    int t = blockIdx.x * blockDim.x + threadIdx.x;
    int e0 = t * 2;
    if (e0 + 1 < EE) {
        int2 r2 = *(const int2*)(ei + e0);
        int2 c2 = *(const int2*)(ei + EE + e0);
        float2 a2 = *(const float2*)(attr + e0);
        int2 p2 = *(const int2*)(g_epos + e0);
        float w0 = -a2.x * g_dinv[r2.x] * g_dinv[c2.x];
        float w1 = -a2.y * g_dinv[r2.y] * g_dinv[c2.y];
        g_edges[g_rowptr[r2.x] + p2.x] = make_int2(c2.x, __float_as_int(w0));
        g_edges[g_rowptr[r2.y] + p2.y] = make_int2(c2.y, __float_as_int(w1));
    } else if (e0 < EE) {
        int r = ei[e0];
        int c = ei[EE + e0];
        float w = -attr[e0] * g_dinv[r] * g_dinv[c];
        g_edges[g_rowptr[r] + g_epos[e0]] = make_int2(c, __float_as_int(w));
    }
}

// ---------------- row gather core: sum over edges of row, fp16 in, fp32 acc ---------
__device__ __forceinline__ float4 gather_row(const uint2* __restrict__ in, int row, int l) {
    int s = g_rowptr[row], e = g_rowptr[row + 1];  // both even
    float4 A = make_float4(0.f, 0.f, 0.f, 0.f);
    float4 B = make_float4(0.f, 0.f, 0.f, 0.f);
    int j = s;
    for (; j + 4 <= e; j += 4) {
        int4 p0 = *(const int4*)(g_edges + j);
        int4 p1 = *(const int4*)(g_edges + j + 2);
        uint2 u0 = in[p0.x * 16 + l];
        uint2 u1 = in[p0.z * 16 + l];
        uint2 u2 = in[p1.x * 16 + l];
        uint2 u3 = in[p1.z * 16 + l];
        float w0 = __int_as_float(p0.y);
        float w1 = __int_as_float(p0.w);
        float w2 = __int_as_float(p1.y);
        float w3 = __int_as_float(p1.w);
        float4 v0 = h4_to_f4(u0);
        float4 v1 = h4_to_f4(u1);
        float4 v2 = h4_to_f4(u2);
        float4 v3 = h4_to_f4(u3);
        A.x = fmaf(w0, v0.x, A.x); A.y = fmaf(w0, v0.y, A.y);
        A.z = fmaf(w0, v0.z, A.z); A.w = fmaf(w0, v0.w, A.w);
        B.x = fmaf(w1, v1.x, B.x); B.y = fmaf(w1, v1.y, B.y);
        B.z = fmaf(w1, v1.z, B.z); B.w = fmaf(w1, v1.w, B.w);
        A.x = fmaf(w2, v2.x, A.x); A.y = fmaf(w2, v2.y, A.y);
        A.z = fmaf(w2, v2.z, A.z); A.w = fmaf(w2, v2.w, A.w);
        B.x = fmaf(w3, v3.x, B.x); B.y = fmaf(w3, v3.y, B.y);
        B.z = fmaf(w3, v3.z, B.z); B.w = fmaf(w3, v3.w, B.w);
    }
    if (j < e) {  // exactly 2 edges left
        int4 p0 = *(const int4*)(g_edges + j);
        uint2 u0 = in[p0.x * 16 + l];
        uint2 u1 = in[p0.z * 16 + l];
        float w0 = __int_as_float(p0.y);
        float w1 = __int_as_float(p0.w);
        float4 v0 = h4_to_f4(u0);
        float4 v1 = h4_to_f4(u1);
        A.x = fmaf(w0, v0.x, A.x); A.y = fmaf(w0, v0.y, A.y);
        A.z = fmaf(w0, v0.z, A.z); A.w = fmaf(w0, v0.w, A.w);
        B.x = fmaf(w1, v1.x, B.x); B.y = fmaf(w1, v1.y, B.y);
        B.z = fmaf(w1, v1.z, B.z); B.w = fmaf(w1, v1.w, B.w);
    }
    return make_float4(A.x + B.x, A.y + B.y, A.z + B.z, A.w + B.w);
}

// ---------------- prop1: persistent, half-warp (16 lanes) per row, T1 = S*in --------
__global__ __launch_bounds__(256, 5) void prop_kernel(const uint2* __restrict__ in,
                                                      uint2* __restrict__ out) {
    int l = threadIdx.x & 15;
    int hw0 = (blockIdx.x * blockDim.x + threadIdx.x) >> 4;
    const int nhw = (PROPBLK * 256) >> 4;  // 11840 half-warps
    for (int row = hw0; row < NN; row += nhw) {
        out[row * 16 + l] = f4_to_h4(gather_row(in, row, l));
    }
}

// ---------------- fused prop2 + GEMM ----------------
// Per 64-row chunk: compute T2 = S*T1 rows directly into smem A-tile slot 2,
// stage x (slot 0) and T1 (slot 1), then wmma GEMM + bias/relu epilogue.
// Bank-conflict-free strides (odd multiples of 16B).
#define SA_STRIDE 200
#define SB_STRIDE 72
#define SC_STRIDE 68
#define SB_OFF (64 * SA_STRIDE * 2)                 // 25600 B
#define SMEM_TOTAL (SB_OFF + 192 * SB_STRIDE * 2)   // 25600 + 27648 = 53248 B
template <bool RELU, bool OUTH>
__global__ __launch_bounds__(256, 4) void propgemm_kernel(
    const uint2* __restrict__ x0, const uint2* __restrict__ t1,
    const __half* __restrict__ Wf, const float* __restrict__ b, void* __restrict__ out) {
    extern __shared__ char smem[];
    __half* sA = (__half*)smem;
    __half* sB = (__half*)(smem + SB_OFF);
    float*  sC = (float*)smem;   // reused after MMA: 64 x SC_STRIDE fp32 = 17408 B

    int tid = threadIdx.x;
    int row0 = blockIdx.x * 64;
    int l = tid & 15;
    int hw = tid >> 4;   // 0..15

    // stage B: pre-folded weights into padded rows (independent of gather)
    for (int i = tid; i < 3072; i += 256) {
        int k = i >> 4, c = i & 15;
        *(uint2*)&sB[k * SB_STRIDE + c * 4] = ((const uint2*)Wf)[i];
    }
    // stage A slots 0 (x) and 1 (T1)
    for (int i = tid; i < 1024; i += 256) {
        int r = i >> 4, c = i & 15;
        int row = row0 + r;
        bool ok = row < NN;
        uint2 v0 = ok ? x0[row * 16 + c] : make_uint2(0u, 0u);
        uint2 v1 = ok ? t1[row * 16 + c] : make_uint2(0u, 0u);
        *(uint2*)&sA[r * SA_STRIDE + c * 4]      = v0;
        *(uint2*)&sA[r * SA_STRIDE + 64 + c * 4] = v1;
    }
    // gather phase: T2 rows straight into slot 2 (16 rows in flight, 4 rounds)
    #pragma unroll
    for (int round = 0; round < 4; round++) {
        int rl = hw + 16 * round;        // local row 0..63
        int row = row0 + rl;
        uint2 res = make_uint2(0u, 0u);
        if (row < NN) res = f4_to_h4(gather_row(t1, row, l));
        *(uint2*)&sA[rl * SA_STRIDE + 128 + l * 4] = res;
    }
    __syncthreads();

    // MMA: warp w -> tiles (wm, wn) and (wm+2, wn)
    int w = tid >> 5;
    int wm = w >> 2;   // 0..1
    int wn = w & 3;    // 0..3
    wmma::fragment<wmma::accumulator, 16, 16, 16, float> acc0, acc1;
    wmma::fill_fragment(acc0, 0.f);
    wmma::fill_fragment(acc1, 0.f);
    #pragma unroll
    for (int k = 0; k < 192; k += 16) {
        wmma::fragment<wmma::matrix_a, 16, 16, 16, __half, wmma::row_major> a0, a1;
        wmma::fragment<wmma::matrix_b, 16, 16, 16, __half, wmma::row_major> bf;
        wmma::load_matrix_sync(a0, sA + (wm * 16) * SA_STRIDE + k, SA_STRIDE);
        wmma::load_matrix_sync(a1, sA + (wm * 16 + 32) * SA_STRIDE + k, SA_STRIDE);
        wmma::load_matrix_sync(bf, sB + k * SB_STRIDE + wn * 16, SB_STRIDE);
        wmma::mma_sync(acc0, a0, bf, acc0);
        wmma::mma_sync(acc1, a1, bf, acc1);
    }
    __syncthreads();  // done reading sA; reuse as sC
    wmma::store_matrix_sync(sC + (wm * 16) * SC_STRIDE + wn * 16, acc0, SC_STRIDE,
                            wmma::mem_row_major);
    wmma::store_matrix_sync(sC + (wm * 16 + 32) * SC_STRIDE + wn * 16, acc1, SC_STRIDE,
                            wmma::mem_row_major);
    __syncthreads();

    // epilogue: bias + relu + store
    for (int i = tid; i < 1024; i += 256) {
        int r = i >> 4, c = i & 15;
        int row = row0 + r;
        if (row < NN) {
            float4 v = *(const float4*)(sC + r * SC_STRIDE + c * 4);
            float4 bias = ((const float4*)b)[c];
            v.x += bias.x; v.y += bias.y; v.z += bias.z; v.w += bias.w;
            if (RELU) {
                v.x = fmaxf(v.x, 0.f); v.y = fmaxf(v.y, 0.f);
                v.z = fmaxf(v.z, 0.f); v.w = fmaxf(v.w, 0.f);
            }
            if (OUTH) {
                ((uint2*)out)[row * 16 + c] = f4_to_h4(v);
            } else {
                ((float4*)out)[row * 16 + c] = v;
            }
        }
    }
}

// ---------------- mean pool per graph + last-block MLP ----------------
__device__ __forceinline__ int lower_bound_batch(const int* b, int val) {
    int lo = 0, hi = NN;
    while (lo < hi) {
        int mid = (lo + hi) >> 1;
        if (b[mid] < val) lo = mid + 1; else hi = mid;
    }
    return lo;
}

__global__ void pool_mlp_kernel(const float* __restrict__ h, const int* __restrict__ batch,
                                const float* __restrict__ Wl1, const float* __restrict__ bl1,
                                const float* __restrict__ Wl2, const float* __restrict__ bl2,
                                float* __restrict__ out) {
    int g = blockIdx.x;
    __shared__ int s_lo, s_hi;
    if (threadIdx.x == 0) {
        s_lo = lower_bound_batch(batch, g);
        s_hi = lower_bound_batch(batch, g + 1);
    }
    __syncthreads();
    int lo = s_lo, hi = s_hi;
    int f = threadIdx.x & 63;
    int part = threadIdx.x >> 6;
    float acc = 0.f;
    for (int i = lo + part; i < hi; i += 4) acc += h[i * 64 + f];
    __shared__ float sh[4][64];
    sh[part][f] = acc;
    __syncthreads();
    if (part == 0) {
        float s = sh[0][f] + sh[1][f] + sh[2][f] + sh[3][f];
        float cnt = (float)(hi - lo);
        g_pool[g * 64 + f] = s / fmaxf(cnt, 1.f);
    }
    __threadfence();
    __shared__ int s_last;
    __syncthreads();
    if (threadIdx.x == 0) {
        int* cnt = (int*)(g_zero + POOLCNT_OFF);
        s_last = (atomicAdd(cnt, 1) == GG - 1);
    }
    __syncthreads();
    if (!s_last) return;
    __threadfence();

    __shared__ float sp[GG * 64];
    __shared__ float sh1[GG * 32];
    int tid = threadIdx.x;
    for (int i = tid; i < GG * 64; i += 256) sp[i] = g_pool[i];
    __syncthreads();
    for (int i = tid; i < GG * 32; i += 256) {
        int gg = i >> 5, c = i & 31;
        float s = bl1[c];
        #pragma unroll 8
        for (int k = 0; k < 64; k++) s += sp[gg * 64 + k] * Wl1[k * 32 + c];
        sh1[i] = fmaxf(s, 0.f);
    }
    __syncthreads();
    for (int i = tid; i < GG * CC; i += 256) {
        int gg = i / CC, c = i % CC;
        float s = bl2[c];
        #pragma unroll
        for (int k = 0; k < 32; k++) s += sh1[gg * 32 + k] * Wl2[k * CC + c];
        out[i] = s;
    }
}

// ---------------- launcher ----------------
extern "C" void kernel_launch(void* const* d_in, const int* in_sizes, int n_in,
                              void* d_out, int out_size) {
    const float* x    = (const float*)d_in[0];
    const int*   ei   = (const int*)d_in[1];
    const float* attr = (const float*)d_in[2];
    const int*   bat  = (const int*)d_in[3];
    const float* W1 = (const float*)d_in[4];
    const float* b1 = (const float*)d_in[5];
    const float* W2 = (const float*)d_in[6];
    const float* b2 = (const float*)d_in[7];
    const float* W3 = (const float*)d_in[8];
    const float* b3 = (const float*)d_in[9];
    const float* Wl1 = (const float*)d_in[10];
    const float* bl1 = (const float*)d_in[11];
    const float* Wl2 = (const float*)d_in[12];
    const float* bl2 = (const float*)d_in[13];
    float* out = (float*)d_out;

    uint2 *xh, *T1, *H0, *H1;
    __half* Wf;
    float *Hf;
    void* zp;
    cudaGetSymbolAddress((void**)&xh, g_xh);
    cudaGetSymbolAddress((void**)&T1, g_T1);
    cudaGetSymbolAddress((void**)&H0, g_H0);
    cudaGetSymbolAddress((void**)&H1, g_H1);
    cudaGetSymbolAddress((void**)&Hf, g_Hf);
    cudaGetSymbolAddress((void**)&Wf, g_Wf);
    cudaGetSymbolAddress(&zp, g_zero);

    cudaFuncSetAttribute((const void*)propgemm_kernel<true, true>,
                         cudaFuncAttributeMaxDynamicSharedMemorySize, SMEM_TOTAL);
    cudaFuncSetAttribute((const void*)propgemm_kernel<false, false>,
                         cudaFuncAttributeMaxDynamicSharedMemorySize, SMEM_TOTAL);

    const int NB_E2 = (EE / 2 + 255) / 256;
    const int NB_G = (NN + 63) / 64;
    const int NB_C = (NN * 16 + 255) / 256;

    cudaMemsetAsync(zp, 0, ZERO_BYTES);
    cvt_kernel<<<NB_C, 256>>>((const float4*)x);
    degw_kernel<<<NB_E2 + 3, 256>>>(ei, attr, W1, W2, W3);
    scan_kernel<<<NBLK, 1024>>>();
    fill_kernel<<<NB_E2, 256>>>(ei, attr);

    // Layer 1: T1 = S*xh; fused (T2 = S*T1 in smem) + GEMM -> H0
    prop_kernel<<<PROPBLK, 256>>>(xh, T1);
    propgemm_kernel<true, true><<<NB_G, 256, SMEM_TOTAL>>>(xh, T1, Wf, b1, H0);
    // Layer 2
    prop_kernel<<<PROPBLK, 256>>>(H0, T1);
    propgemm_kernel<true, true><<<NB_G, 256, SMEM_TOTAL>>>(H0, T1, Wf + 192 * 64, b2, H1);
    // Layer 3 (fp32 output for pooling)
    prop_kernel<<<PROPBLK, 256>>>(H1, T1);
    propgemm_kernel<false, false><<<NB_G, 256, SMEM_TOTAL>>>(H1, T1, Wf + 2 * 192 * 64, b3, Hf);

    pool_mlp_kernel<<<GG, 256>>>(Hf, bat, Wl1, bl1, Wl2, bl2, out);
}

// round 17
// speedup vs baseline: 1.0155x; 1.0155x over previous
#include <cuda_runtime.h>
#include <cuda_fp16.h>
#include <mma.h>

using namespace nvcuda;

#define NN 50000
#define EE 800000
#define ECAP (EE + NN)   // padded edge capacity (each row padded to even count)
#define F 64
#define GG 64
#define CC 10
#define NBLK 49      // ceil(NN/1024)
#define PROPBLK 740  // 148 SMs x 5 resident CTAs
#define CVTBLK 3125  // NN*16/256

typedef unsigned long long ull;

// ---------------- scratch (device globals; no allocation allowed) ----------------
#define WDEG_OFF    0
#define DEGCNT_OFF  (NN * 4)
#define STATE_OFF   (2 * NN * 4)
#define POOLCNT_OFF (STATE_OFF + 64 * 8)
#define ZERO_BYTES  (POOLCNT_OFF + 16)
__device__ __align__(16) unsigned char g_zero[ZERO_BYTES];

__device__ __align__(16) float  g_dinv[NN];
__device__ __align__(16) int    g_rowptr[NN + 1];
__device__ __align__(16) int    g_epos[EE];      // per-edge slot within its row
__device__ __align__(16) int2   g_edges[ECAP];   // (col, bitcast(norm)), even-padded rows
__device__ __align__(16) __half g_xh[NN * F];    // fp16 copy of x
__device__ __align__(16) __half g_T1[NN * F];
__device__ __align__(16) __half g_T2[NN * F];
__device__ __align__(16) __half g_H0[NN * F];
__device__ __align__(16) __half g_H1[NN * F];
__device__ __align__(16) float  g_Hf[NN * F];    // fp32 final layer output
__device__ __align__(16) float  g_pool[GG * F];
__device__ __align__(16) __half g_Wf[3 * 192 * 64];  // pre-folded fp16 weights

// fp16 pack/unpack helpers (8 bytes = 4 features)
__device__ __forceinline__ float4 h4_to_f4(uint2 u) {
    float2 a = __half22float2(*reinterpret_cast<const __half2*>(&u.x));
    float2 b = __half22float2(*reinterpret_cast<const __half2*>(&u.y));
    return make_float4(a.x, a.y, b.x, b.y);
}
__device__ __forceinline__ uint2 f4_to_h4(float4 v) {
    __half2 a = __floats2half2_rn(v.x, v.y);
    __half2 b = __floats2half2_rn(v.z, v.w);
    uint2 u;
    u.x = *reinterpret_cast<unsigned*>(&a);
    u.y = *reinterpret_cast<unsigned*>(&b);
    return u;
}

// ---------------- fused build: W-fold (3) + x->fp16 cvt (3125) + degree (rest) ------
__global__ void degw_kernel(const int* __restrict__ ei, const float* __restrict__ attr,
                            const float* __restrict__ x,
                            const float* __restrict__ W1, const float* __restrict__ W2,
                            const float* __restrict__ W3) {
    if (blockIdx.x < 3) {
        int b = blockIdx.x;
        const float* W = (b == 0) ? W1 : (b == 1) ? W2 : W3;
        __half* dst = g_Wf + b * 192 * 64;
        int tid = threadIdx.x;
        for (int i = tid; i < 1024; i += 256) {
            int k = i >> 4, c = i & 15;
            float4 w0 = ((const float4*)W)[i];
            float4 w1 = ((const float4*)W)[1024 + i];
            float4 w2 = ((const float4*)W)[2048 + i];
            float4 f0 = make_float4(w0.x - w2.x, w0.y - w2.y, w0.z - w2.z, w0.w - w2.w);
            float4 f2 = make_float4(2.f * w2.x, 2.f * w2.y, 2.f * w2.z, 2.f * w2.w);
            *(uint2*)&dst[k * 64 + c * 4]         = f4_to_h4(f0);
            *(uint2*)&dst[(64 + k) * 64 + c * 4]  = f4_to_h4(w1);
            *(uint2*)&dst[(128 + k) * 64 + c * 4] = f4_to_h4(f2);
        }
        return;
    }
    if (blockIdx.x < 3 + CVTBLK) {
        int i = (blockIdx.x - 3) * 256 + threadIdx.x;
        if (i < NN * 16) {
            ((uint2*)g_xh)[i] = f4_to_h4(((const float4*)x)[i]);
        }
        return;
    }
    float* wdeg = (float*)(g_zero + WDEG_OFF);
    int* degcnt = (int*)(g_zero + DEGCNT_OFF);
    int t = (blockIdx.x - 3 - CVTBLK) * blockDim.x + threadIdx.x;
    int e0 = t * 2;
    if (e0 + 1 < EE) {
        int2 r2 = *(const int2*)(ei + e0);
        float2 a2 = *(const float2*)(attr + e0);
        atomicAdd(&wdeg[r2.x], a2.x);
        atomicAdd(&wdeg[r2.y], a2.y);
        g_epos[e0]     = atomicAdd(&degcnt[r2.x], 1);
        g_epos[e0 + 1] = atomicAdd(&degcnt[r2.y], 1);
    } else if (e0 < EE) {
        int r = ei[e0];
        atomicAdd(&wdeg[r], attr[e0]);
        g_epos[e0] = atomicAdd(&degcnt[r], 1);
    }
}

// Single-kernel scan over EVEN-PADDED degrees + dinv + rowptr init + hole edges.
__global__ void scan_kernel() {
    float* wdeg = (float*)(g_zero + WDEG_OFF);
    int* degcnt = (int*)(g_zero + DEGCNT_OFF);
    volatile ull* state = (volatile ull*)(g_zero + STATE_OFF);

    int tid = threadIdx.x;
    int b = blockIdx.x;
    int i = b * 1024 + tid;
    int deg = (i < NN) ? degcnt[i] : 0;
    int pdeg = (deg + 1) & ~1;   // padded to even

    if (i < NN) {
        float d = wdeg[i];
        g_dinv[i] = (d > 0.f) ? rsqrtf(d) : 0.f;
    }

    int lane = tid & 31, wid = tid >> 5;
    int x = pdeg;
    #pragma unroll
    for (int o = 1; o < 32; o <<= 1) {
        int y = __shfl_up_sync(0xFFFFFFFFu, x, o);
        if (lane >= o) x += y;
    }
    __shared__ int ws[32];
    __shared__ int s_prefix;
    if (lane == 31) ws[wid] = x;
    __syncthreads();
    if (wid == 0) {
        int s = ws[lane];
        #pragma unroll
        for (int o = 1; o < 32; o <<= 1) {
            int y = __shfl_up_sync(0xFFFFFFFFu, s, o);
            if (lane >= o) s += y;
        }
        ws[lane] = s;
    }
    __syncthreads();
    int blocksum = ws[31];

    if (tid == 0) {
        atomicExch((ull*)&state[b], (1ull << 32) | (unsigned)blocksum);
    }
    if (tid < 32) {
        int acc = 0;
        for (int p = tid; p < b; p += 32) {
            ull sv;
            do { sv = state[p]; } while ((sv >> 32) == 0);
            acc += (int)(unsigned)sv;
        }
        #pragma unroll
        for (int o = 16; o > 0; o >>= 1) acc += __shfl_down_sync(0xFFFFFFFFu, acc, o);
        if (tid == 0) s_prefix = acc;
    }
    __syncthreads();

    int excl = x - pdeg + (wid > 0 ? ws[wid - 1] : 0);
    if (i < NN) {
        int r = excl + s_prefix;
        g_rowptr[i] = r;
        if (deg & 1) g_edges[r + deg] = make_int2(0, 0);  // neutral hole edge
    }
    if (b == NBLK - 1 && tid == 0) g_rowptr[NN] = s_prefix + blocksum;
}

// Atomic-free fill: slot precomputed in degw (epos), pure scatter stores.
__global__ void fill_kernel(const int* __restrict__ ei, const float* __restrict__ attr) {
    int t = blockIdx.x * blockDim.x + threadIdx.x;
    int e0 = t * 2;
    if (e0 + 1 < EE) {
        int2 r2 = *(const int2*)(ei + e0);
        int2 c2 = *(const int2*)(ei + EE + e0);
        float2 a2 = *(const float2*)(attr + e0);
        int2 p2 = *(const int2*)(g_epos + e0);
        float w0 = -a2.x * g_dinv[r2.x] * g_dinv[c2.x];
        float w1 = -a2.y * g_dinv[r2.y] * g_dinv[c2.y];
        g_edges[g_rowptr[r2.x] + p2.x] = make_int2(c2.x, __float_as_int(w0));
        g_edges[g_rowptr[r2.y] + p2.y] = make_int2(c2.y, __float_as_int(w1));
    } else if (e0 < EE) {
        int r = ei[e0];
        int c = ei[EE + e0];
        float w = -attr[e0] * g_dinv[r] * g_dinv[c];
        g_edges[g_rowptr[r] + g_epos[e0]] = make_int2(c, __float_as_int(w));
    }
}

// ---------------- row gather core: sum over edges of row, fp16 in, fp32 acc ---------
__device__ __forceinline__ float4 gather_row(const uint2* __restrict__ in, int row, int l) {
    int s = g_rowptr[row], e = g_rowptr[row + 1];  // both even
    float4 A = make_float4(0.f, 0.f, 0.f, 0.f);
    float4 B = make_float4(0.f, 0.f, 0.f, 0.f);
    int j = s;
    for (; j + 4 <= e; j += 4) {
        int4 p0 = *(const int4*)(g_edges + j);
        int4 p1 = *(const int4*)(g_edges + j + 2);
        uint2 u0 = in[p0.x * 16 + l];
        uint2 u1 = in[p0.z * 16 + l];
        uint2 u2 = in[p1.x * 16 + l];
        uint2 u3 = in[p1.z * 16 + l];
        float w0 = __int_as_float(p0.y);
        float w1 = __int_as_float(p0.w);
        float w2 = __int_as_float(p1.y);
        float w3 = __int_as_float(p1.w);
        float4 v0 = h4_to_f4(u0);
        float4 v1 = h4_to_f4(u1);
        float4 v2 = h4_to_f4(u2);
        float4 v3 = h4_to_f4(u3);
        A.x = fmaf(w0, v0.x, A.x); A.y = fmaf(w0, v0.y, A.y);
        A.z = fmaf(w0, v0.z, A.z); A.w = fmaf(w0, v0.w, A.w);
        B.x = fmaf(w1, v1.x, B.x); B.y = fmaf(w1, v1.y, B.y);
        B.z = fmaf(w1, v1.z, B.z); B.w = fmaf(w1, v1.w, B.w);
        A.x = fmaf(w2, v2.x, A.x); A.y = fmaf(w2, v2.y, A.y);
        A.z = fmaf(w2, v2.z, A.z); A.w = fmaf(w2, v2.w, A.w);
        B.x = fmaf(w3, v3.x, B.x); B.y = fmaf(w3, v3.y, B.y);
        B.z = fmaf(w3, v3.z, B.z); B.w = fmaf(w3, v3.w, B.w);
    }
    if (j < e) {  // exactly 2 edges left
        int4 p0 = *(const int4*)(g_edges + j);
        uint2 u0 = in[p0.x * 16 + l];
        uint2 u1 = in[p0.z * 16 + l];
        float w0 = __int_as_float(p0.y);
        float w1 = __int_as_float(p0.w);
        float4 v0 = h4_to_f4(u0);
        float4 v1 = h4_to_f4(u1);
        A.x = fmaf(w0, v0.x, A.x); A.y = fmaf(w0, v0.y, A.y);
        A.z = fmaf(w0, v0.z, A.z); A.w = fmaf(w0, v0.w, A.w);
        B.x = fmaf(w1, v1.x, B.x); B.y = fmaf(w1, v1.y, B.y);
        B.z = fmaf(w1, v1.z, B.z); B.w = fmaf(w1, v1.w, B.w);
    }
    return make_float4(A.x + B.x, A.y + B.y, A.z + B.z, A.w + B.w);
}

// ---------------- prop: persistent, half-warp (16 lanes) per row, out = S*in --------
__global__ __launch_bounds__(256, 5) void prop_kernel(const uint2* __restrict__ in,
                                                      uint2* __restrict__ out) {
    int l = threadIdx.x & 15;
    int hw0 = (blockIdx.x * blockDim.x + threadIdx.x) >> 4;
    const int nhw = (PROPBLK * 256) >> 4;  // 11840 half-warps
    for (int row = hw0; row < NN; row += nhw) {
        out[row * 16 + l] = f4_to_h4(gather_row(in, row, l));
    }
}

// ---------------- tensor-core GEMM: out = relu?([x|T1|U] @ Wf + b) ----------------
// Bank-conflict-free strides (odd multiples of 16B). Per-warp epilogue: each warp
// stores + reads back only its own sC region -> no final block barrier.
#define SA_STRIDE 200
#define SB_STRIDE 72
#define SC_STRIDE 68
#define SB_OFF (64 * SA_STRIDE * 2)                 // 25600 B
#define SMEM_TOTAL (SB_OFF + 192 * SB_STRIDE * 2)   // 25600 + 27648 = 53248 B
template <bool RELU, bool OUTH>
__global__ __launch_bounds__(256, 4) void gemm3_kernel(
    const uint2* __restrict__ x0, const uint2* __restrict__ x1, const uint2* __restrict__ x2,
    const __half* __restrict__ Wf, const float* __restrict__ b, void* __restrict__ out) {
    extern __shared__ char smem[];
    __half* sA = (__half*)smem;
    __half* sB = (__half*)(smem + SB_OFF);
    float*  sC = (float*)smem;    // reused after MMA: 64 x SC_STRIDE fp32 = 17408 B

    int tid = threadIdx.x;
    int row0 = blockIdx.x * 64;

    // stage A (fp16 passthrough)
    #pragma unroll
    for (int m = 0; m < 3; m++) {
        const uint2* src = (m == 0) ? x0 : (m == 1) ? x1 : x2;
        for (int i = tid; i < 1024; i += 256) {
            int r = i >> 4, c = i & 15;
            int row = row0 + r;
            uint2 v = (row < NN) ? src[row * 16 + c] : make_uint2(0u, 0u);
            *(uint2*)&sA[r * SA_STRIDE + m * 64 + c * 4] = v;
        }
    }
    // stage B: copy pre-folded weights into padded rows
    for (int i = tid; i < 3072; i += 256) {
        int k = i >> 4, c = i & 15;
        *(uint2*)&sB[k * SB_STRIDE + c * 4] = ((const uint2*)Wf)[i];
    }
    __syncthreads();

    // MMA: warp w -> tiles (wm, wn) and (wm+2, wn)
    int w = tid >> 5;
    int lane = tid & 31;
    int wm = w >> 2;   // 0..1
    int wn = w & 3;    // 0..3
    wmma::fragment<wmma::accumulator, 16, 16, 16, float> acc0, acc1;
    wmma::fill_fragment(acc0, 0.f);
    wmma::fill_fragment(acc1, 0.f);
    #pragma unroll
    for (int k = 0; k < 192; k += 16) {
        wmma::fragment<wmma::matrix_a, 16, 16, 16, __half, wmma::row_major> a0, a1;
        wmma::fragment<wmma::matrix_b, 16, 16, 16, __half, wmma::row_major> bf;
        wmma::load_matrix_sync(a0, sA + (wm * 16) * SA_STRIDE + k, SA_STRIDE);
        wmma::load_matrix_sync(a1, sA + (wm * 16 + 32) * SA_STRIDE + k, SA_STRIDE);
        wmma::load_matrix_sync(bf, sB + k * SB_STRIDE + wn * 16, SB_STRIDE);
        wmma::mma_sync(acc0, a0, bf, acc0);
        wmma::mma_sync(acc1, a1, bf, acc1);
    }
    __syncthreads();  // all warps done reading sA; safe to overwrite as sC

    // per-warp epilogue: warp stores its own tiles, reads back only its own region
    wmma::store_matrix_sync(sC + (wm * 16) * SC_STRIDE + wn * 16, acc0, SC_STRIDE,
                            wmma::mem_row_major);
    wmma::store_matrix_sync(sC + (wm * 16 + 32) * SC_STRIDE + wn * 16, acc1, SC_STRIDE,
                            wmma::mem_row_major);
    __syncwarp();

    float2 bias2 = ((const float2*)b)[wn * 8 + (lane & 7)];
    #pragma unroll
    for (int half = 0; half < 2; half++) {
        int rbase = wm * 16 + half * 32;
        // 16 rows x 16 cols, 32 lanes: each lane does 8 elems as float2
        #pragma unroll
        for (int rr = 0; rr < 4; rr++) {
            int r = rbase + (lane >> 3) + rr * 4;       // local row
            int c2 = wn * 8 + (lane & 7);               // float2 col index within 64
            int row = row0 + r;
            if (row < NN) {
                float2 v = *(const float2*)(sC + r * SC_STRIDE + (lane & 7) * 2 + wn * 16);
                v.x += bias2.x; v.y += bias2.y;
                if (RELU) { v.x = fmaxf(v.x, 0.f); v.y = fmaxf(v.y, 0.f); }
                if (OUTH) {
                    __half2 h = __floats2half2_rn(v.x, v.y);
                    ((unsigned*)out)[row * 32 + c2] = *reinterpret_cast<unsigned*>(&h);
                } else {
                    ((float2*)out)[row * 32 + c2] = v;
                }
            }
        }
    }
}

// ---------------- mean pool per graph + last-block MLP ----------------
__device__ __forceinline__ int lower_bound_batch(const int* b, int val) {
    int lo = 0, hi = NN;
    while (lo < hi) {
        int mid = (lo + hi) >> 1;
        if (b[mid] < val) lo = mid + 1; else hi = mid;
    }
    return lo;
}

__global__ void pool_mlp_kernel(const float* __restrict__ h, const int* __restrict__ batch,
                                const float* __restrict__ Wl1, const float* __restrict__ bl1,
                                const float* __restrict__ Wl2, const float* __restrict__ bl2,
                                float* __restrict__ out) {
    int g = blockIdx.x;
    __shared__ int s_lo, s_hi;
    if (threadIdx.x == 0) {
        s_lo = lower_bound_batch(batch, g);
        s_hi = lower_bound_batch(batch, g + 1);
    }
    __syncthreads();
    int lo = s_lo, hi = s_hi;
    int f = threadIdx.x & 63;
    int part = threadIdx.x >> 6;
    float acc = 0.f;
    for (int i = lo + part; i < hi; i += 4) acc += h[i * 64 + f];
    __shared__ float sh[4][64];
    sh[part][f] = acc;
    __syncthreads();
    if (part == 0) {
        float s = sh[0][f] + sh[1][f] + sh[2][f] + sh[3][f];
        float cnt = (float)(hi - lo);
        g_pool[g * 64 + f] = s / fmaxf(cnt, 1.f);
    }
    __threadfence();
    __shared__ int s_last;
    __syncthreads();
    if (threadIdx.x == 0) {
        int* cnt = (int*)(g_zero + POOLCNT_OFF);
        s_last = (atomicAdd(cnt, 1) == GG - 1);
    }
    __syncthreads();
    if (!s_last) return;
    __threadfence();

    __shared__ float sp[GG * 64];
    __shared__ float sh1[GG * 32];
    int tid = threadIdx.x;
    for (int i = tid; i < GG * 64; i += 256) sp[i] = g_pool[i];
    __syncthreads();
    for (int i = tid; i < GG * 32; i += 256) {
        int gg = i >> 5, c = i & 31;
        float s = bl1[c];
        #pragma unroll 8
        for (int k = 0; k < 64; k++) s += sp[gg * 64 + k] * Wl1[k * 32 + c];
        sh1[i] = fmaxf(s, 0.f);
    }
    __syncthreads();
    for (int i = tid; i < GG * CC; i += 256) {
        int gg = i / CC, c = i % CC;
        float s = bl2[c];
        #pragma unroll
        for (int k = 0; k < 32; k++) s += sh1[gg * 32 + k] * Wl2[k * CC + c];
        out[i] = s;
    }
}

// ---------------- launcher ----------------
extern "C" void kernel_launch(void* const* d_in, const int* in_sizes, int n_in,
                              void* d_out, int out_size) {
    const float* x    = (const float*)d_in[0];
    const int*   ei   = (const int*)d_in[1];
    const float* attr = (const float*)d_in[2];
    const int*   bat  = (const int*)d_in[3];
    const float* W1 = (const float*)d_in[4];
    const float* b1 = (const float*)d_in[5];
    const float* W2 = (const float*)d_in[6];
    const float* b2 = (const float*)d_in[7];
    const float* W3 = (const float*)d_in[8];
    const float* b3 = (const float*)d_in[9];
    const float* Wl1 = (const float*)d_in[10];
    const float* bl1 = (const float*)d_in[11];
    const float* Wl2 = (const float*)d_in[12];
    const float* bl2 = (const float*)d_in[13];
    float* out = (float*)d_out;

    uint2 *xh, *T1, *T2, *H0, *H1;
    __half* Wf;
    float *Hf;
    void* zp;
    cudaGetSymbolAddress((void**)&xh, g_xh);
    cudaGetSymbolAddress((void**)&T1, g_T1);
    cudaGetSymbolAddress((void**)&T2, g_T2);
    cudaGetSymbolAddress((void**)&H0, g_H0);
    cudaGetSymbolAddress((void**)&H1, g_H1);
    cudaGetSymbolAddress((void**)&Hf, g_Hf);
    cudaGetSymbolAddress((void**)&Wf, g_Wf);
    cudaGetSymbolAddress(&zp, g_zero);

    cudaFuncSetAttribute((const void*)gemm3_kernel<true, true>,
                         cudaFuncAttributeMaxDynamicSharedMemorySize, SMEM_TOTAL);
    cudaFuncSetAttribute((const void*)gemm3_kernel<false, false>,
                         cudaFuncAttributeMaxDynamicSharedMemorySize, SMEM_TOTAL);

    const int NB_E2 = (EE / 2 + 255) / 256;
    const int NB_G = (NN + 63) / 64;

    cudaMemsetAsync(zp, 0, ZERO_BYTES);
    degw_kernel<<<3 + CVTBLK + NB_E2, 256>>>(ei, attr, x, W1, W2, W3);
    scan_kernel<<<NBLK, 1024>>>();
    fill_kernel<<<NB_E2, 256>>>(ei, attr);

    // Layer 1: T1 = S*xh, U = S*T1, H0 = relu([xh|T1|U] @ Wf1 + b1)
    prop_kernel<<<PROPBLK, 256>>>(xh, T1);
    prop_kernel<<<PROPBLK, 256>>>(T1, T2);
    gemm3_kernel<true, true><<<NB_G, 256, SMEM_TOTAL>>>(xh, T1, T2, Wf, b1, H0);
    // Layer 2
    prop_kernel<<<PROPBLK, 256>>>(H0, T1);
    prop_kernel<<<PROPBLK, 256>>>(T1, T2);
    gemm3_kernel<true, true><<<NB_G, 256, SMEM_TOTAL>>>(H0, T1, T2, Wf + 192 * 64, b2, H1);
    // Layer 3 (fp32 output for pooling)
    prop_kernel<<<PROPBLK, 256>>>(H1, T1);
    prop_kernel<<<PROPBLK, 256>>>(T1, T2);
    gemm3_kernel<false, false><<<NB_G, 256, SMEM_TOTAL>>>(H1, T1, T2, Wf + 2 * 192 * 64, b3, Hf);

    pool_mlp_kernel<<<GG, 256>>>(Hf, bat, Wl1, bl1, Wl2, bl2, out);
}